// round 5
// baseline (speedup 1.0000x reference)
#include <cuda_runtime.h>
#include <cstdint>

#define BB 2048
#define TT 512
#define KK 32
#define FULL 0xFFFFFFFFu
#define NEG_INF (-3.402823466e+38f)

// Backpointer scratch: 2048 * 512 * 32 bytes = 32 MB (write-streaming; backtrace hits L2)
__device__ unsigned char g_bp[(size_t)BB * TT * KK];

// One block = 64 threads = 2 warps = 1 batch element.
// warp 0: Viterbi forward + backtrace + tags/best_score
// warp 1: logsumexp forward + sequence score + log_likelihood

__global__ __launch_bounds__(64)
void crf_kernel(const float* __restrict__ pot,
                const float* __restrict__ trans,
                const int*   __restrict__ lens,
                const int*   __restrict__ tags_in,
                float*       __restrict__ out)
{
    __shared__ float s_trans[KK * KK];          // 4 KB
    __shared__ float s_abc[2][KK];              // alpha broadcast, double buf
    __shared__ float s_ebc[2][KK];              // exp(beta-m) broadcast, double buf
    __shared__ unsigned char s_tg[TT];          // decoded tags staging

    const int tid  = threadIdx.x;
    const int lane = tid & 31;
    const int role = tid >> 5;
    const int b    = blockIdx.x;

    for (int i = tid; i < KK * KK; i += 64) s_trans[i] = trans[i];
    __syncthreads();

    const float* potb = pot + (size_t)b * TT * KK;
    const int len = lens[b];

    if (role == 0) {
        // ---------------- Viterbi warp ----------------
        float tcol[KK];
#pragma unroll
        for (int i = 0; i < KK; ++i) tcol[i] = s_trans[i * KK + lane];

        unsigned char* bpb = g_bp + (size_t)b * TT * KK;

        float alpha = potb[lane];
        float ptn   = potb[KK + lane];               // prefetch t=1 (always in-bounds)

        for (int t = 1; t < len; ++t) {
            const float ptc = ptn;
            const int tn = (t + 1 < TT) ? t + 1 : t;
            ptn = potb[(size_t)tn * KK + lane];

            float* sa = &s_abc[t & 1][0];
            sa[lane] = alpha;
            __syncwarp();
            const float4* sav = (const float4*)sa;

            // 4 blocked chains: chain c covers kp in [8c, 8c+8)
            float bv0 = NEG_INF, bv1 = NEG_INF, bv2 = NEG_INF, bv3 = NEG_INF;
            int   bi0 = 0, bi1 = 0, bi2 = 0, bi3 = 0;
#pragma unroll
            for (int j = 0; j < 8; ++j) {
                const float4 a4 = sav[j];
                const int kb = j * 4;
                const float s0 = a4.x + tcol[kb + 0];
                const float s1 = a4.y + tcol[kb + 1];
                const float s2 = a4.z + tcol[kb + 2];
                const float s3 = a4.w + tcol[kb + 3];
                if ((j >> 1) == 0) {
                    if (s0 > bv0) { bv0 = s0; bi0 = kb + 0; }
                    if (s1 > bv0) { bv0 = s1; bi0 = kb + 1; }
                    if (s2 > bv0) { bv0 = s2; bi0 = kb + 2; }
                    if (s3 > bv0) { bv0 = s3; bi0 = kb + 3; }
                } else if ((j >> 1) == 1) {
                    if (s0 > bv1) { bv1 = s0; bi1 = kb + 0; }
                    if (s1 > bv1) { bv1 = s1; bi1 = kb + 1; }
                    if (s2 > bv1) { bv1 = s2; bi1 = kb + 2; }
                    if (s3 > bv1) { bv1 = s3; bi1 = kb + 3; }
                } else if ((j >> 1) == 2) {
                    if (s0 > bv2) { bv2 = s0; bi2 = kb + 0; }
                    if (s1 > bv2) { bv2 = s1; bi2 = kb + 1; }
                    if (s2 > bv2) { bv2 = s2; bi2 = kb + 2; }
                    if (s3 > bv2) { bv2 = s3; bi2 = kb + 3; }
                } else {
                    if (s0 > bv3) { bv3 = s0; bi3 = kb + 0; }
                    if (s1 > bv3) { bv3 = s1; bi3 = kb + 1; }
                    if (s2 > bv3) { bv3 = s2; bi3 = kb + 2; }
                    if (s3 > bv3) { bv3 = s3; bi3 = kb + 3; }
                }
            }
            // combine in ascending-kp order with strict > : exact first-index tie-break
            float best = bv0; int bk = bi0;
            if (bv1 > best) { best = bv1; bk = bi1; }
            if (bv2 > best) { best = bv2; bk = bi2; }
            if (bv3 > best) { best = bv3; bk = bi3; }

            alpha = ptc + best;
            bpb[(size_t)t * KK + lane] = (unsigned char)bk;
        }

        // warp argmax over lanes (first index on ties)
        float bs = alpha;
        int   bt = lane;
#pragma unroll
        for (int o = 16; o > 0; o >>= 1) {
            const float ov = __shfl_xor_sync(FULL, bs, o);
            const int   oi = __shfl_xor_sync(FULL, bt, o);
            if (ov > bs || (ov == bs && oi < bt)) { bs = ov; bt = oi; }
        }

        __syncwarp();   // order bp stores before lane 0's loads (same warp)
        if (lane == 0) {
            int carry = bt;
            for (int t = TT - 1; t >= len - 1; --t) s_tg[t] = (unsigned char)carry;
            for (int t = len - 1; t >= 1; --t) {
                carry = bpb[(size_t)t * KK + carry];
                s_tg[t - 1] = (unsigned char)carry;
            }
        }
        __syncwarp();

        // outputs: tags [B*T] (coalesced), best_score [B]
        for (int t = lane; t < TT; t += 32)
            out[(size_t)b * TT + t] = (float)s_tg[t];
        if (lane == 0)
            out[(size_t)BB * TT + b] = bs;

    } else {
        // ---------------- logsumexp warp ----------------
        float ecol[KK];
#pragma unroll
        for (int i = 0; i < KK; ++i) ecol[i] = expf(s_trans[i * KK + lane]);

        float beta = potb[lane];
        float ptn  = potb[KK + lane];

        for (int t = 1; t < len; ++t) {
            const float ptc = ptn;
            const int tn = (t + 1 < TT) ? t + 1 : t;
            ptn = potb[(size_t)tn * KK + lane];

            // stabilizer: any warp-uniform value near max works; lane 0's beta
            // is within ~12 of the warp max (pot-spread + transition-spread),
            // so exp(beta - m) <= e^12 — no overflow, negligible error.
            const float m = __shfl_sync(FULL, beta, 0);
            const float e = __expf(beta - m);

            float* se = &s_ebc[t & 1][0];
            se[lane] = e;
            __syncwarp();
            const float4* sev = (const float4*)se;

            float a0 = 0.f, a1 = 0.f, a2 = 0.f, a3 = 0.f;
#pragma unroll
            for (int j = 0; j < 8; ++j) {
                const float4 e4 = sev[j];
                const int kb = j * 4;
                float p = fmaf(e4.x, ecol[kb + 0],
                          fmaf(e4.y, ecol[kb + 1],
                          fmaf(e4.z, ecol[kb + 2],
                               e4.w * ecol[kb + 3])));
                if      ((j >> 1) == 0) a0 += p;
                else if ((j >> 1) == 1) a1 += p;
                else if ((j >> 1) == 2) a2 += p;
                else                    a3 += p;
            }
            beta = ptc + m + __logf((a0 + a1) + (a2 + a3));
        }

        // log_norm = logsumexp over lanes of beta (full-precision reduce)
        float m2 = beta;
#pragma unroll
        for (int o = 16; o > 0; o >>= 1)
            m2 = fmaxf(m2, __shfl_xor_sync(FULL, m2, o));
        float s2 = __expf(beta - m2);
#pragma unroll
        for (int o = 16; o > 0; o >>= 1)
            s2 += __shfl_xor_sync(FULL, s2, o);
        const float logZ = m2 + logf(s2);

        // sequence score: unary (t < len) + binary (t < len-1)
        const int* tagb = tags_in + (size_t)b * TT;
        float ss = 0.0f;
        for (int t = lane; t < TT; t += 32) {
            const int tg = tagb[t];
            if (t < len)     ss += potb[(size_t)t * KK + tg];
            if (t + 1 < len) ss += s_trans[tg * KK + tagb[t + 1]];
        }
#pragma unroll
        for (int o = 16; o > 0; o >>= 1)
            ss += __shfl_xor_sync(FULL, ss, o);

        if (lane == 0)
            out[(size_t)BB * TT + BB + b] = ss - logZ;
    }
}

extern "C" void kernel_launch(void* const* d_in, const int* in_sizes, int n_in,
                              void* d_out, int out_size)
{
    const float* potentials       = (const float*)d_in[0];
    const float* transitions      = (const float*)d_in[1];
    const int*   sequence_lengths = (const int*)d_in[2];
    const int*   tag_indices      = (const int*)d_in[3];
    float*       out              = (float*)d_out;

    crf_kernel<<<BB, 64>>>(potentials, transitions, sequence_lengths,
                           tag_indices, out);
}

// round 6
// speedup vs baseline: 2.7244x; 2.7244x over previous
#include <cuda_runtime.h>
#include <cstdint>

#define BB 2048
#define TT 512
#define KK 32
#define FULL 0xFFFFFFFFu
#define NEG_INF (-3.402823466e+38f)

// One block = 128 threads = 4 warps = 2 batch elements.
// warp (2p+0): Viterbi forward + backtrace + tags/best_score for b = 2*blockIdx+p
// warp (2p+1): logsumexp forward + sequence score + log_likelihood for same b

__global__ __launch_bounds__(128)
void crf_kernel(const float* __restrict__ pot,
                const float* __restrict__ trans,
                const int*   __restrict__ lens,
                const int*   __restrict__ tags_in,
                float*       __restrict__ out)
{
    __shared__ float s_trans[KK * KK];                 // 4 KB
    __shared__ float s_abc[2][2][KK];                  // alpha broadcast, double buf
    __shared__ float s_ebc[2][2][KK];                  // exp(beta-m) broadcast, double buf
    __shared__ unsigned char s_bp[2][TT][KK];          // 32 KB backpointers
    __shared__ unsigned char s_tg[2][TT];              // decoded tags staging

    const int tid  = threadIdx.x;
    const int lane = tid & 31;
    const int w    = tid >> 5;
    const int pair = w >> 1;
    const int role = w & 1;
    const int b    = blockIdx.x * 2 + pair;

    for (int i = tid; i < KK * KK; i += 128) s_trans[i] = trans[i];
    __syncthreads();

    const float* potb = pot + (size_t)b * TT * KK;
    const int len = lens[b];

    if (role == 0) {
        // ---------------- Viterbi warp ----------------
        float tcol[KK];
#pragma unroll
        for (int i = 0; i < KK; ++i) tcol[i] = s_trans[i * KK + lane];

        float alpha = potb[lane];

        // 4-deep prefetch pipeline for the pot stream (DRAM latency ~600-1000cyc;
        // one-step lookahead (~130cyc of work) cannot hide it — 4 can, mostly).
        float p0 = potb[(size_t)1 * KK + lane];
        float p1 = potb[(size_t)2 * KK + lane];
        float p2 = potb[(size_t)3 * KK + lane];
        float p3 = potb[(size_t)4 * KK + lane];

#pragma unroll 4
        for (int t = 1; t < len; ++t) {
            const float ptc = p0;
            p0 = p1; p1 = p2; p2 = p3;
            int tn = t + 4; tn = (tn < TT) ? tn : TT - 1;
            p3 = potb[(size_t)tn * KK + lane];

            float* sa = &s_abc[pair][t & 1][0];
            sa[lane] = alpha;
            __syncwarp();
            const float4* sav = (const float4*)sa;

            // 4 blocked chains: chain c covers kp in [8c, 8c+8)
            float bv0 = NEG_INF, bv1 = NEG_INF, bv2 = NEG_INF, bv3 = NEG_INF;
            int   bi0 = 0, bi1 = 0, bi2 = 0, bi3 = 0;
#pragma unroll
            for (int j = 0; j < 8; ++j) {
                const float4 a4 = sav[j];
                const int kb = j * 4;
                const float s0 = a4.x + tcol[kb + 0];
                const float s1 = a4.y + tcol[kb + 1];
                const float s2 = a4.z + tcol[kb + 2];
                const float s3 = a4.w + tcol[kb + 3];
                if ((j >> 1) == 0) {
                    if (s0 > bv0) { bv0 = s0; bi0 = kb + 0; }
                    if (s1 > bv0) { bv0 = s1; bi0 = kb + 1; }
                    if (s2 > bv0) { bv0 = s2; bi0 = kb + 2; }
                    if (s3 > bv0) { bv0 = s3; bi0 = kb + 3; }
                } else if ((j >> 1) == 1) {
                    if (s0 > bv1) { bv1 = s0; bi1 = kb + 0; }
                    if (s1 > bv1) { bv1 = s1; bi1 = kb + 1; }
                    if (s2 > bv1) { bv1 = s2; bi1 = kb + 2; }
                    if (s3 > bv1) { bv1 = s3; bi1 = kb + 3; }
                } else if ((j >> 1) == 2) {
                    if (s0 > bv2) { bv2 = s0; bi2 = kb + 0; }
                    if (s1 > bv2) { bv2 = s1; bi2 = kb + 1; }
                    if (s2 > bv2) { bv2 = s2; bi2 = kb + 2; }
                    if (s3 > bv2) { bv2 = s3; bi2 = kb + 3; }
                } else {
                    if (s0 > bv3) { bv3 = s0; bi3 = kb + 0; }
                    if (s1 > bv3) { bv3 = s1; bi3 = kb + 1; }
                    if (s2 > bv3) { bv3 = s2; bi3 = kb + 2; }
                    if (s3 > bv3) { bv3 = s3; bi3 = kb + 3; }
                }
            }
            // combine in ascending-kp order with strict > : exact first-index tie-break
            float best = bv0; int bk = bi0;
            if (bv1 > best) { best = bv1; bk = bi1; }
            if (bv2 > best) { best = bv2; bk = bi2; }
            if (bv3 > best) { best = bv3; bk = bi3; }

            alpha = ptc + best;
            s_bp[pair][t][lane] = (unsigned char)bk;
        }

        // warp argmax over lanes (first index on ties)
        float bs = alpha;
        int   bt = lane;
#pragma unroll
        for (int o = 16; o > 0; o >>= 1) {
            const float ov = __shfl_xor_sync(FULL, bs, o);
            const int   oi = __shfl_xor_sync(FULL, bt, o);
            if (ov > bs || (ov == bs && oi < bt)) { bs = ov; bt = oi; }
        }

        __syncwarp();   // all s_bp writes visible to lane 0
        if (lane == 0) {
            unsigned char* st = s_tg[pair];
            int carry = bt;
            for (int t = TT - 1; t >= len - 1; --t) st[t] = (unsigned char)carry;
            for (int t = len - 1; t >= 1; --t) {
                carry = s_bp[pair][t][carry];
                st[t - 1] = (unsigned char)carry;
            }
        }
        __syncwarp();

        // outputs: tags [B*T] (coalesced), best_score [B]
        for (int t = lane; t < TT; t += 32)
            out[(size_t)b * TT + t] = (float)s_tg[pair][t];
        if (lane == 0)
            out[(size_t)BB * TT + b] = bs;

    } else {
        // ---------------- logsumexp warp ----------------
        float ecol[KK];
#pragma unroll
        for (int i = 0; i < KK; ++i) ecol[i] = expf(s_trans[i * KK + lane]);

        float beta = potb[lane];

        float p0 = potb[(size_t)1 * KK + lane];
        float p1 = potb[(size_t)2 * KK + lane];
        float p2 = potb[(size_t)3 * KK + lane];
        float p3 = potb[(size_t)4 * KK + lane];

#pragma unroll 4
        for (int t = 1; t < len; ++t) {
            const float ptc = p0;
            p0 = p1; p1 = p2; p2 = p3;
            int tn = t + 4; tn = (tn < TT) ? tn : TT - 1;
            p3 = potb[(size_t)tn * KK + lane];

            // stabilizer: any warp-uniform value near the max works; lane 0's
            // beta is within ~12 of the warp max (pot + transition spread),
            // so exp(beta - m) <= e^12 — no overflow, negligible error.
            const float m = __shfl_sync(FULL, beta, 0);
            const float e = __expf(beta - m);

            float* se = &s_ebc[pair][t & 1][0];
            se[lane] = e;
            __syncwarp();
            const float4* sev = (const float4*)se;

            float a0 = 0.f, a1 = 0.f, a2 = 0.f, a3 = 0.f;
#pragma unroll
            for (int j = 0; j < 8; ++j) {
                const float4 e4 = sev[j];
                const int kb = j * 4;
                float p = fmaf(e4.x, ecol[kb + 0],
                          fmaf(e4.y, ecol[kb + 1],
                          fmaf(e4.z, ecol[kb + 2],
                               e4.w * ecol[kb + 3])));
                if      ((j >> 1) == 0) a0 += p;
                else if ((j >> 1) == 1) a1 += p;
                else if ((j >> 1) == 2) a2 += p;
                else                    a3 += p;
            }
            beta = ptc + m + __logf((a0 + a1) + (a2 + a3));
        }

        // log_norm = logsumexp over lanes of beta (full-precision reduce)
        float m2 = beta;
#pragma unroll
        for (int o = 16; o > 0; o >>= 1)
            m2 = fmaxf(m2, __shfl_xor_sync(FULL, m2, o));
        float s2 = __expf(beta - m2);
#pragma unroll
        for (int o = 16; o > 0; o >>= 1)
            s2 += __shfl_xor_sync(FULL, s2, o);
        const float logZ = m2 + logf(s2);

        // sequence score: unary (t < len) + binary (t < len-1)
        const int* tagb = tags_in + (size_t)b * TT;
        float ss = 0.0f;
        for (int t = lane; t < TT; t += 32) {
            const int tg = tagb[t];
            if (t < len)     ss += potb[(size_t)t * KK + tg];
            if (t + 1 < len) ss += s_trans[tg * KK + tagb[t + 1]];
        }
#pragma unroll
        for (int o = 16; o > 0; o >>= 1)
            ss += __shfl_xor_sync(FULL, ss, o);

        if (lane == 0)
            out[(size_t)BB * TT + BB + b] = ss - logZ;
    }
}

extern "C" void kernel_launch(void* const* d_in, const int* in_sizes, int n_in,
                              void* d_out, int out_size)
{
    const float* potentials       = (const float*)d_in[0];
    const float* transitions      = (const float*)d_in[1];
    const int*   sequence_lengths = (const int*)d_in[2];
    const int*   tag_indices      = (const int*)d_in[3];
    float*       out              = (float*)d_out;

    crf_kernel<<<BB / 2, 128>>>(potentials, transitions, sequence_lengths,
                                tag_indices, out);
}

// round 7
// speedup vs baseline: 2.7800x; 1.0204x over previous
#include <cuda_runtime.h>
#include <cstdint>

#define BB 2048
#define TT 512
#define KK 32
#define FULL 0xFFFFFFFFu
#define NEG_INF (-3.402823466e+38f)

// Schedule: batch indices sorted by descending sequence length (LPT).
__device__ unsigned short g_sched[BB];

// ---------------------------------------------------------------------------
// Pre-pass: counting sort of batch indices by descending length.
// One block, 512 threads. lens are in [1, 512].
// ---------------------------------------------------------------------------
__global__ __launch_bounds__(512)
void sched_kernel(const int* __restrict__ lens)
{
    __shared__ int h[TT + 1];     // h[L] = count of jobs with len == L
    __shared__ int sc[TT];        // scan workspace (reversed order)
    __shared__ int ctr[TT + 1];   // running output cursor per length

    const int tid = threadIdx.x;  // 0..511

    h[tid] = 0;
    if (tid == 0) h[TT] = 0;
    __syncthreads();

    for (int b = tid; b < BB; b += 512) atomicAdd(&h[lens[b]], 1);
    __syncthreads();

    // reversed array: r=0 <-> len=512. inclusive Hillis-Steele scan.
    const int r = tid;
    const int v = h[TT - r];
    sc[r] = v;
    __syncthreads();
#pragma unroll
    for (int d = 1; d < TT; d <<= 1) {
        const int add = (r >= d) ? sc[r - d] : 0;
        __syncthreads();
        sc[r] += add;
        __syncthreads();
    }
    // offset for len L = sum of counts of lens > L  (exclusive scan value)
    ctr[TT - r] = sc[r] - v;
    __syncthreads();

    for (int b = tid; b < BB; b += 512) {
        const int pos = atomicAdd(&ctr[lens[b]], 1);
        g_sched[pos] = (unsigned short)b;
    }
}

// ---------------------------------------------------------------------------
// Main kernel: one block = 64 threads = 2 warps = 1 batch element.
// warp 0: Viterbi forward + backtrace + tags/best_score
// warp 1: logsumexp forward + sequence score + log_likelihood
// ---------------------------------------------------------------------------
__global__ __launch_bounds__(64)
void crf_kernel(const float* __restrict__ pot,
                const float* __restrict__ trans,
                const int*   __restrict__ lens,
                const int*   __restrict__ tags_in,
                float*       __restrict__ out)
{
    __shared__ float s_trans[KK * KK];          // 4 KB
    __shared__ float s_abc[2][KK];              // alpha broadcast, double buf
    __shared__ float s_ebc[2][KK];              // exp(beta-m) broadcast, double buf
    __shared__ unsigned char s_bp[TT][KK];      // 16 KB backpointers
    __shared__ unsigned char s_tg[TT];          // decoded tags staging

    const int tid  = threadIdx.x;
    const int lane = tid & 31;
    const int role = tid >> 5;
    const int b    = g_sched[blockIdx.x];       // LPT order: longest first

    for (int i = tid; i < KK * KK; i += 64) s_trans[i] = trans[i];
    __syncthreads();

    const float* potb = pot + (size_t)b * TT * KK;
    const int len = lens[b];

    if (role == 0) {
        // ---------------- Viterbi warp ----------------
        float tcol[KK];
#pragma unroll
        for (int i = 0; i < KK; ++i) tcol[i] = s_trans[i * KK + lane];

        float alpha = potb[lane];

        // 4-deep prefetch pipeline for the pot stream (covers DRAM latency)
        float p0 = potb[(size_t)1 * KK + lane];
        float p1 = potb[(size_t)2 * KK + lane];
        float p2 = potb[(size_t)3 * KK + lane];
        float p3 = potb[(size_t)4 * KK + lane];

#pragma unroll 4
        for (int t = 1; t < len; ++t) {
            const float ptc = p0;
            p0 = p1; p1 = p2; p2 = p3;
            int tn = t + 4; tn = (tn < TT) ? tn : TT - 1;
            p3 = potb[(size_t)tn * KK + lane];

            float* sa = &s_abc[t & 1][0];
            sa[lane] = alpha;
            __syncwarp();
            const float4* sav = (const float4*)sa;

            // 4 blocked chains: chain c covers kp in [8c, 8c+8)
            float bv0 = NEG_INF, bv1 = NEG_INF, bv2 = NEG_INF, bv3 = NEG_INF;
            int   bi0 = 0, bi1 = 0, bi2 = 0, bi3 = 0;
#pragma unroll
            for (int j = 0; j < 8; ++j) {
                const float4 a4 = sav[j];
                const int kb = j * 4;
                const float s0 = a4.x + tcol[kb + 0];
                const float s1 = a4.y + tcol[kb + 1];
                const float s2 = a4.z + tcol[kb + 2];
                const float s3 = a4.w + tcol[kb + 3];
                if ((j >> 1) == 0) {
                    if (s0 > bv0) { bv0 = s0; bi0 = kb + 0; }
                    if (s1 > bv0) { bv0 = s1; bi0 = kb + 1; }
                    if (s2 > bv0) { bv0 = s2; bi0 = kb + 2; }
                    if (s3 > bv0) { bv0 = s3; bi0 = kb + 3; }
                } else if ((j >> 1) == 1) {
                    if (s0 > bv1) { bv1 = s0; bi1 = kb + 0; }
                    if (s1 > bv1) { bv1 = s1; bi1 = kb + 1; }
                    if (s2 > bv1) { bv1 = s2; bi1 = kb + 2; }
                    if (s3 > bv1) { bv1 = s3; bi1 = kb + 3; }
                } else if ((j >> 1) == 2) {
                    if (s0 > bv2) { bv2 = s0; bi2 = kb + 0; }
                    if (s1 > bv2) { bv2 = s1; bi2 = kb + 1; }
                    if (s2 > bv2) { bv2 = s2; bi2 = kb + 2; }
                    if (s3 > bv2) { bv2 = s3; bi2 = kb + 3; }
                } else {
                    if (s0 > bv3) { bv3 = s0; bi3 = kb + 0; }
                    if (s1 > bv3) { bv3 = s1; bi3 = kb + 1; }
                    if (s2 > bv3) { bv3 = s2; bi3 = kb + 2; }
                    if (s3 > bv3) { bv3 = s3; bi3 = kb + 3; }
                }
            }
            // combine in ascending-kp order with strict > : exact first-index tie-break
            float best = bv0; int bk = bi0;
            if (bv1 > best) { best = bv1; bk = bi1; }
            if (bv2 > best) { best = bv2; bk = bi2; }
            if (bv3 > best) { best = bv3; bk = bi3; }

            alpha = ptc + best;
            s_bp[t][lane] = (unsigned char)bk;
        }

        // warp argmax over lanes (first index on ties)
        float bs = alpha;
        int   bt = lane;
#pragma unroll
        for (int o = 16; o > 0; o >>= 1) {
            const float ov = __shfl_xor_sync(FULL, bs, o);
            const int   oi = __shfl_xor_sync(FULL, bt, o);
            if (ov > bs || (ov == bs && oi < bt)) { bs = ov; bt = oi; }
        }

        __syncwarp();   // all s_bp writes visible to lane 0
        if (lane == 0) {
            int carry = bt;
            for (int t = TT - 1; t >= len - 1; --t) s_tg[t] = (unsigned char)carry;
            for (int t = len - 1; t >= 1; --t) {
                carry = s_bp[t][carry];
                s_tg[t - 1] = (unsigned char)carry;
            }
        }
        __syncwarp();

        // outputs: tags [B*T] (coalesced), best_score [B]
        for (int t = lane; t < TT; t += 32)
            out[(size_t)b * TT + t] = (float)s_tg[t];
        if (lane == 0)
            out[(size_t)BB * TT + b] = bs;

    } else {
        // ---------------- logsumexp warp ----------------
        float ecol[KK];
#pragma unroll
        for (int i = 0; i < KK; ++i) ecol[i] = expf(s_trans[i * KK + lane]);

        float beta = potb[lane];

        float p0 = potb[(size_t)1 * KK + lane];
        float p1 = potb[(size_t)2 * KK + lane];
        float p2 = potb[(size_t)3 * KK + lane];
        float p3 = potb[(size_t)4 * KK + lane];

#pragma unroll 4
        for (int t = 1; t < len; ++t) {
            const float ptc = p0;
            p0 = p1; p1 = p2; p2 = p3;
            int tn = t + 4; tn = (tn < TT) ? tn : TT - 1;
            p3 = potb[(size_t)tn * KK + lane];

            // stabilizer: any warp-uniform value near the max works; lane 0's
            // beta is within ~12 of the warp max (pot + transition spread),
            // so exp(beta - m) <= e^12 — no overflow, negligible error.
            const float m = __shfl_sync(FULL, beta, 0);
            const float e = __expf(beta - m);

            float* se = &s_ebc[t & 1][0];
            se[lane] = e;
            __syncwarp();
            const float4* sev = (const float4*)se;

            float a0 = 0.f, a1 = 0.f, a2 = 0.f, a3 = 0.f;
#pragma unroll
            for (int j = 0; j < 8; ++j) {
                const float4 e4 = sev[j];
                const int kb = j * 4;
                float p = fmaf(e4.x, ecol[kb + 0],
                          fmaf(e4.y, ecol[kb + 1],
                          fmaf(e4.z, ecol[kb + 2],
                               e4.w * ecol[kb + 3])));
                if      ((j >> 1) == 0) a0 += p;
                else if ((j >> 1) == 1) a1 += p;
                else if ((j >> 1) == 2) a2 += p;
                else                    a3 += p;
            }
            beta = ptc + m + __logf((a0 + a1) + (a2 + a3));
        }

        // log_norm = logsumexp over lanes of beta (full-precision reduce)
        float m2 = beta;
#pragma unroll
        for (int o = 16; o > 0; o >>= 1)
            m2 = fmaxf(m2, __shfl_xor_sync(FULL, m2, o));
        float s2 = __expf(beta - m2);
#pragma unroll
        for (int o = 16; o > 0; o >>= 1)
            s2 += __shfl_xor_sync(FULL, s2, o);
        const float logZ = m2 + logf(s2);

        // sequence score: unary (t < len) + binary (t < len-1)
        const int* tagb = tags_in + (size_t)b * TT;
        float ss = 0.0f;
        for (int t = lane; t < TT; t += 32) {
            const int tg = tagb[t];
            if (t < len)     ss += potb[(size_t)t * KK + tg];
            if (t + 1 < len) ss += s_trans[tg * KK + tagb[t + 1]];
        }
#pragma unroll
        for (int o = 16; o > 0; o >>= 1)
            ss += __shfl_xor_sync(FULL, ss, o);

        if (lane == 0)
            out[(size_t)BB * TT + BB + b] = ss - logZ;
    }
}

extern "C" void kernel_launch(void* const* d_in, const int* in_sizes, int n_in,
                              void* d_out, int out_size)
{
    const float* potentials       = (const float*)d_in[0];
    const float* transitions      = (const float*)d_in[1];
    const int*   sequence_lengths = (const int*)d_in[2];
    const int*   tag_indices      = (const int*)d_in[3];
    float*       out              = (float*)d_out;

    sched_kernel<<<1, 512>>>(sequence_lengths);
    crf_kernel<<<BB, 64>>>(potentials, transitions, sequence_lengths,
                           tag_indices, out);
}

// round 8
// speedup vs baseline: 3.4268x; 1.2327x over previous
#include <cuda_runtime.h>
#include <cstdint>

#define BB 2048
#define TT 512
#define KK 32
#define FULL 0xFFFFFFFFu
#define NEG_INF (-3.402823466e+38f)

// Schedule: batch indices sorted by descending sequence length (LPT).
__device__ unsigned short g_sched[BB];

// ---------------------------------------------------------------------------
// Pre-pass: counting sort of batch indices by descending length.
// One block, 512 threads. lens are in [1, 512].
// ---------------------------------------------------------------------------
__global__ __launch_bounds__(512)
void sched_kernel(const int* __restrict__ lens)
{
    __shared__ int h[TT + 1];     // h[L] = count of jobs with len == L
    __shared__ int sc[TT];        // scan workspace (reversed order)
    __shared__ int ctr[TT + 1];   // running output cursor per length

    const int tid = threadIdx.x;  // 0..511

    h[tid] = 0;
    if (tid == 0) h[TT] = 0;
    __syncthreads();

    for (int b = tid; b < BB; b += 512) atomicAdd(&h[lens[b]], 1);
    __syncthreads();

    // reversed array: r=0 <-> len=512. inclusive Hillis-Steele scan.
    const int r = tid;
    const int v = h[TT - r];
    sc[r] = v;
    __syncthreads();
#pragma unroll
    for (int d = 1; d < TT; d <<= 1) {
        const int add = (r >= d) ? sc[r - d] : 0;
        __syncthreads();
        sc[r] += add;
        __syncthreads();
    }
    // offset for len L = sum of counts of lens > L  (exclusive scan value)
    ctr[TT - r] = sc[r] - v;
    __syncthreads();

    for (int b = tid; b < BB; b += 512) {
        const int pos = atomicAdd(&ctr[lens[b]], 1);
        g_sched[pos] = (unsigned short)b;
    }
}

// ---------------------------------------------------------------------------
// Main kernel: one block = 64 threads = 2 warps = 2 batch elements.
// Each warp does BOTH recurrences (Viterbi + logsumexp) for its job:
// the two chains are independent -> 2x per-warp ILP, pot loaded once,
// one combined (alpha, e) broadcast per step.
// ---------------------------------------------------------------------------
__global__ __launch_bounds__(64)
void crf_kernel(const float* __restrict__ pot,
                const float* __restrict__ trans,
                const int*   __restrict__ lens,
                const int*   __restrict__ tags_in,
                float*       __restrict__ out)
{
    __shared__ float s_trans[KK * KK];                     // 4 KB
    __shared__ __align__(16) float2 s_ab[2][2][KK];        // [warp][buf][lane]=(alpha,e), 1 KB
    __shared__ unsigned char s_bp[2][TT][KK];              // 32 KB backpointers
    __shared__ unsigned char s_tg[2][TT];                  // 1 KB decoded tags

    const int tid  = threadIdx.x;
    const int lane = tid & 31;
    const int w    = tid >> 5;
    const int b    = g_sched[blockIdx.x * 2 + w];          // LPT: adjacent lengths pair

    for (int i = tid; i < KK * KK; i += 64) s_trans[i] = trans[i];
    __syncthreads();

    const float* potb = pot + (size_t)b * TT * KK;
    const int len = lens[b];

    // Per-lane transition column (kcur = lane) and its exp
    float tcol[KK];
    float ecol[KK];
#pragma unroll
    for (int i = 0; i < KK; ++i) {
        tcol[i] = s_trans[i * KK + lane];
        ecol[i] = expf(tcol[i]);
    }

    float alpha = potb[lane];   // Viterbi state
    float beta  = alpha;        // logsumexp state

    // 4-deep prefetch pipeline for the single shared pot stream
    float p0 = potb[(size_t)1 * KK + lane];
    float p1 = potb[(size_t)2 * KK + lane];
    float p2 = potb[(size_t)3 * KK + lane];
    float p3 = potb[(size_t)4 * KK + lane];

#pragma unroll 2
    for (int t = 1; t < len; ++t) {
        const float ptc = p0;
        p0 = p1; p1 = p2; p2 = p3;
        int tn = t + 4; tn = (tn < TT) ? tn : TT - 1;
        p3 = potb[(size_t)tn * KK + lane];

        // stabilizer: warp-uniform lane-0 beta (within ~12 of warp max ->
        // exp(beta-m) <= e^12, no overflow, negligible error)
        const float m = __shfl_sync(FULL, beta, 0);
        const float e = __expf(beta - m);

        float2* sab = &s_ab[w][t & 1][0];
        sab[lane] = make_float2(alpha, e);
        __syncwarp();
        const float4* sv = (const float4*)sab;   // sv[j] = {a2j, e2j, a2j+1, e2j+1}

        // Viterbi: 4 blocked argmax chains; lse: 4 blocked fma chains
        float bv0 = NEG_INF, bv1 = NEG_INF, bv2 = NEG_INF, bv3 = NEG_INF;
        int   bi0 = 0, bi1 = 0, bi2 = 0, bi3 = 0;
        float a0 = 0.f, a1 = 0.f, a2 = 0.f, a3 = 0.f;
#pragma unroll
        for (int j = 0; j < 16; ++j) {
            const float4 v4 = sv[j];
            const int kb = j * 2;
            const float s0 = v4.x + tcol[kb + 0];
            const float s1 = v4.z + tcol[kb + 1];
            const float pr = fmaf(v4.y, ecol[kb + 0], v4.w * ecol[kb + 1]);
            if ((j >> 2) == 0) {
                if (s0 > bv0) { bv0 = s0; bi0 = kb + 0; }
                if (s1 > bv0) { bv0 = s1; bi0 = kb + 1; }
                a0 += pr;
            } else if ((j >> 2) == 1) {
                if (s0 > bv1) { bv1 = s0; bi1 = kb + 0; }
                if (s1 > bv1) { bv1 = s1; bi1 = kb + 1; }
                a1 += pr;
            } else if ((j >> 2) == 2) {
                if (s0 > bv2) { bv2 = s0; bi2 = kb + 0; }
                if (s1 > bv2) { bv2 = s1; bi2 = kb + 1; }
                a2 += pr;
            } else {
                if (s0 > bv3) { bv3 = s0; bi3 = kb + 0; }
                if (s1 > bv3) { bv3 = s1; bi3 = kb + 1; }
                a3 += pr;
            }
        }
        // combine in ascending-kp order with strict > : exact first-index tie-break
        float best = bv0; int bk = bi0;
        if (bv1 > best) { best = bv1; bk = bi1; }
        if (bv2 > best) { best = bv2; bk = bi2; }
        if (bv3 > best) { best = bv3; bk = bi3; }

        alpha = ptc + best;
        beta  = ptc + m + __logf((a0 + a1) + (a2 + a3));
        s_bp[w][t][lane] = (unsigned char)bk;
    }

    // ---- Viterbi epilogue: warp argmax over lanes (first index on ties) ----
    float bs = alpha;
    int   bt = lane;
#pragma unroll
    for (int o = 16; o > 0; o >>= 1) {
        const float ov = __shfl_xor_sync(FULL, bs, o);
        const int   oi = __shfl_xor_sync(FULL, bt, o);
        if (ov > bs || (ov == bs && oi < bt)) { bs = ov; bt = oi; }
    }

    __syncwarp();   // all s_bp writes visible to lane 0
    if (lane == 0) {
        unsigned char* st = s_tg[w];
        int carry = bt;
        for (int t = TT - 1; t >= len - 1; --t) st[t] = (unsigned char)carry;
        for (int t = len - 1; t >= 1; --t) {
            carry = s_bp[w][t][carry];
            st[t - 1] = (unsigned char)carry;
        }
    }
    __syncwarp();

    // outputs: tags [B*T] (coalesced), best_score [B]
    for (int t = lane; t < TT; t += 32)
        out[(size_t)b * TT + t] = (float)s_tg[w][t];
    if (lane == 0)
        out[(size_t)BB * TT + b] = bs;

    // ---- lse epilogue: log_norm (full-precision lane reduce) ----
    float m2 = beta;
#pragma unroll
    for (int o = 16; o > 0; o >>= 1)
        m2 = fmaxf(m2, __shfl_xor_sync(FULL, m2, o));
    float s2 = __expf(beta - m2);
#pragma unroll
    for (int o = 16; o > 0; o >>= 1)
        s2 += __shfl_xor_sync(FULL, s2, o);
    const float logZ = m2 + logf(s2);

    // sequence score: unary (t < len) + binary (t < len-1)
    const int* tagb = tags_in + (size_t)b * TT;
    float ss = 0.0f;
    for (int t = lane; t < TT; t += 32) {
        const int tg = tagb[t];
        if (t < len)     ss += potb[(size_t)t * KK + tg];
        if (t + 1 < len) ss += s_trans[tg * KK + tagb[t + 1]];
    }
#pragma unroll
    for (int o = 16; o > 0; o >>= 1)
        ss += __shfl_xor_sync(FULL, ss, o);

    if (lane == 0)
        out[(size_t)BB * TT + BB + b] = ss - logZ;
}

extern "C" void kernel_launch(void* const* d_in, const int* in_sizes, int n_in,
                              void* d_out, int out_size)
{
    const float* potentials       = (const float*)d_in[0];
    const float* transitions      = (const float*)d_in[1];
    const int*   sequence_lengths = (const int*)d_in[2];
    const int*   tag_indices      = (const int*)d_in[3];
    float*       out              = (float*)d_out;

    sched_kernel<<<1, 512>>>(sequence_lengths);
    crf_kernel<<<BB / 2, 64>>>(potentials, transitions, sequence_lengths,
                               tag_indices, out);
}